// round 1
// baseline (speedup 1.0000x reference)
#include <cuda_runtime.h>

#define NN 50000
#define EE 800000

// ---------------- scratch (static device globals; no allocation) ----------------
__device__ float g_deg[NN];
__device__ float g_h  [NN * 128];   // layer output ping (reused each layer)
__device__ float g_yl [NN * 128];   // neighbor-linear pre-aggregation
__device__ float g_yr [NN * 128];   // root-linear
__device__ float g_agg[NN * 128];   // scatter accumulator

// ---------------- small utility kernels ----------------
__global__ void zero_deg_kernel() {
    int i = blockIdx.x * blockDim.x + threadIdx.x;
    if (i < NN) g_deg[i] = 0.0f;
}

__global__ void deg_kernel(const int* __restrict__ ei) {
    int i = blockIdx.x * blockDim.x + threadIdx.x;
    if (i < EE) atomicAdd(&g_deg[ei[EE + i]], 1.0f);
}

__global__ void zero_agg_kernel(int n4) {
    int i = blockIdx.x * blockDim.x + threadIdx.x;
    if (i < n4) ((float4*)g_agg)[i] = make_float4(0.f, 0.f, 0.f, 0.f);
}

// ---------------- dual GEMM: y[l|r] = X @ W[l|r]^T ----------------
// Whole concatenated weight (2*DOUT x 128) resident in SMEM, k-major, padded pitch.
// 256 threads, each computes 8 rows x 4 cols.
template <int DOUT, bool USE_H>
__global__ void __launch_bounds__(256, 1)
gemm_kernel(const float* __restrict__ Xext,
            const float* __restrict__ Wl,
            const float* __restrict__ Wr)
{
    constexpr int K  = 128;
    constexpr int D2 = 2 * DOUT;
    constexpr int CG = D2 / 4;        // column groups (4 cols each)
    constexpr int RG = 256 / CG;      // row groups
    constexpr int BM = RG * 8;        // rows per block
    constexpr int WP = D2 + 4;        // Ws pitch (floats)
    constexpr int XP = BM + 4;        // Xs pitch (floats)

    extern __shared__ float sm[];
    float* Ws = sm;              // K * WP
    float* Xs = sm + K * WP;     // K * XP

    const float* X = USE_H ? (const float*)g_h : Xext;

    const int tid  = threadIdx.x;
    const int row0 = blockIdx.x * BM;

    // load weights: Ws[k*WP + c] = (c < DOUT ? Wl[c][k] : Wr[c-DOUT][k])
    for (int idx = tid; idx < D2 * K; idx += 256) {
        int c = idx / K, k = idx % K;
        float v = (c < DOUT) ? Wl[c * K + k] : Wr[(c - DOUT) * K + k];
        Ws[k * WP + c] = v;
    }
    // load X tile transposed: Xs[k*XP + r]
    for (int idx = tid; idx < BM * K; idx += 256) {
        int r = idx / K, k = idx % K;
        int grow = row0 + r;
        Xs[k * XP + r] = (grow < NN) ? X[grow * K + k] : 0.0f;
    }
    __syncthreads();

    const int cg  = tid % CG;
    const int rg  = tid / CG;
    const int col = cg * 4;
    const int rb  = rg * 8;

    float acc[8][4];
#pragma unroll
    for (int r = 0; r < 8; r++)
#pragma unroll
        for (int c = 0; c < 4; c++) acc[r][c] = 0.0f;

#pragma unroll 4
    for (int k = 0; k < K; k++) {
        float4 w  = *(const float4*)&Ws[k * WP + col];
        float4 xa = *(const float4*)&Xs[k * XP + rb];
        float4 xb = *(const float4*)&Xs[k * XP + rb + 4];
        float xr[8] = {xa.x, xa.y, xa.z, xa.w, xb.x, xb.y, xb.z, xb.w};
        float wc[4] = {w.x, w.y, w.z, w.w};
#pragma unroll
        for (int r = 0; r < 8; r++)
#pragma unroll
            for (int c = 0; c < 4; c++)
                acc[r][c] += xr[r] * wc[c];
    }

#pragma unroll
    for (int r = 0; r < 8; r++) {
        int grow = row0 + rb + r;
        if (grow < NN) {
            float4 o = make_float4(acc[r][0], acc[r][1], acc[r][2], acc[r][3]);
            if (col < DOUT)
                *(float4*)&g_yl[grow * DOUT + col] = o;
            else
                *(float4*)&g_yr[grow * DOUT + col - DOUT] = o;
        }
    }
}

// ---------------- edge scatter: agg[dst] += yl[src] (vector RED) ----------------
template <int DOUT>
__global__ void scatter_kernel(const int* __restrict__ ei)
{
    constexpr int V = DOUT / 4;
    int gid = blockIdx.x * blockDim.x + threadIdx.x;
    if (gid >= EE * V) return;
    int e = gid / V, v = gid % V;
    int s = ei[e];
    int d = ei[EE + e];
    float4 val = ((const float4*)g_yl)[s * V + v];
    float4* addr = ((float4*)g_agg) + d * V + v;
    asm volatile("red.global.add.v4.f32 [%0], {%1, %2, %3, %4};"
                 :: "l"(addr), "f"(val.x), "f"(val.y), "f"(val.z), "f"(val.w)
                 : "memory");
}

// ---------------- finalize: mean + bias + root + BN (+ReLU) -> g_h ----------------
template <int DOUT, bool RELU>
__global__ void finalize_kernel(const float* __restrict__ bl,
                                const float* __restrict__ g,
                                const float* __restrict__ b,
                                const float* __restrict__ rm,
                                const float* __restrict__ rv)
{
    constexpr int V = DOUT / 4;
    int gid = blockIdx.x * blockDim.x + threadIdx.x;
    if (gid >= NN * V) return;
    int n = gid / V, v = gid % V;
    float inv = 1.0f / fmaxf(g_deg[n], 1.0f);
    float4 a  = ((const float4*)g_agg)[gid];
    float4 y  = ((const float4*)g_yr)[gid];
    float4 BL = ((const float4*)bl)[v];
    float4 G  = ((const float4*)g)[v];
    float4 B  = ((const float4*)b)[v];
    float4 RM = ((const float4*)rm)[v];
    float4 RV = ((const float4*)rv)[v];

    float4 o;
    o.x = (a.x * inv + BL.x + y.x - RM.x) * (G.x * rsqrtf(RV.x + 1e-5f)) + B.x;
    o.y = (a.y * inv + BL.y + y.y - RM.y) * (G.y * rsqrtf(RV.y + 1e-5f)) + B.y;
    o.z = (a.z * inv + BL.z + y.z - RM.z) * (G.z * rsqrtf(RV.z + 1e-5f)) + B.z;
    o.w = (a.w * inv + BL.w + y.w - RM.w) * (G.w * rsqrtf(RV.w + 1e-5f)) + B.w;
    if (RELU) {
        o.x = fmaxf(o.x, 0.f); o.y = fmaxf(o.y, 0.f);
        o.z = fmaxf(o.z, 0.f); o.w = fmaxf(o.w, 0.f);
    }
    ((float4*)g_h)[gid] = o;
}

// ---------------- layer 2 finalize + row L2 normalize -> out ----------------
__global__ void finalize_norm_kernel(const float* __restrict__ bl,
                                     const float* __restrict__ g,
                                     const float* __restrict__ b,
                                     const float* __restrict__ rm,
                                     const float* __restrict__ rv,
                                     float* __restrict__ out)
{
    int t = blockIdx.x * blockDim.x + threadIdx.x;
    int node = t >> 5;
    int lane = t & 31;
    if (node >= NN) return;
    float inv = 1.0f / fmaxf(g_deg[node], 1.0f);
    int idx = node * 32 + lane;           // float2 index (64 cols = 32 float2)
    float2 a  = ((const float2*)g_agg)[idx];
    float2 y  = ((const float2*)g_yr)[idx];
    float2 BL = ((const float2*)bl)[lane];
    float2 G  = ((const float2*)g)[lane];
    float2 B  = ((const float2*)b)[lane];
    float2 RM = ((const float2*)rm)[lane];
    float2 RV = ((const float2*)rv)[lane];

    float v0 = (a.x * inv + BL.x + y.x - RM.x) * (G.x * rsqrtf(RV.x + 1e-5f)) + B.x;
    float v1 = (a.y * inv + BL.y + y.y - RM.y) * (G.y * rsqrtf(RV.y + 1e-5f)) + B.y;

    float s = v0 * v0 + v1 * v1;
#pragma unroll
    for (int off = 16; off > 0; off >>= 1)
        s += __shfl_xor_sync(0xffffffffu, s, off);

    float scale = 1.0f / fmaxf(sqrtf(s), 1e-12f);
    float2 o = make_float2(v0 * scale, v1 * scale);
    ((float2*)out)[idx] = o;
}

// ---------------- launch ----------------
extern "C" void kernel_launch(void* const* d_in, const int* in_sizes, int n_in,
                              void* d_out, int out_size)
{
    const float* x  = (const float*)d_in[0];
    const int*   ei = (const int*)d_in[1];
    auto P = [&](int layer, int j) { return (const float*)d_in[2 + layer * 7 + j]; };
    // j: 0=Wl, 1=bl, 2=Wr, 3=g, 4=b, 5=rm, 6=rv

    const int SMEM128 = (128 * (256 + 4) + 128 * (32 + 4)) * 4;  // 151552
    const int SMEM64  = (128 * (128 + 4) + 128 * (64 + 4)) * 4;  // 102400
    cudaFuncSetAttribute(gemm_kernel<128, false>, cudaFuncAttributeMaxDynamicSharedMemorySize, SMEM128);
    cudaFuncSetAttribute(gemm_kernel<128, true>,  cudaFuncAttributeMaxDynamicSharedMemorySize, SMEM128);
    cudaFuncSetAttribute(gemm_kernel<64,  true>,  cudaFuncAttributeMaxDynamicSharedMemorySize, SMEM64);

    // degree (graph-only, once per call)
    zero_deg_kernel<<<(NN + 255) / 256, 256>>>();
    deg_kernel<<<(EE + 255) / 256, 256>>>(ei);

    // ---- layer 0 (din=128, dout=128, relu) ----
    gemm_kernel<128, false><<<(NN + 31) / 32, 256, SMEM128>>>(x, P(0, 0), P(0, 2));
    zero_agg_kernel<<<(NN * 32 + 255) / 256, 256>>>(NN * 32);
    scatter_kernel<128><<<(EE * 32 + 255) / 256, 256>>>(ei);
    finalize_kernel<128, true><<<(NN * 32 + 255) / 256, 256>>>(P(0, 1), P(0, 3), P(0, 4), P(0, 5), P(0, 6));

    // ---- layer 1 (128 -> 128, relu) ----
    gemm_kernel<128, true><<<(NN + 31) / 32, 256, SMEM128>>>(nullptr, P(1, 0), P(1, 2));
    zero_agg_kernel<<<(NN * 32 + 255) / 256, 256>>>(NN * 32);
    scatter_kernel<128><<<(EE * 32 + 255) / 256, 256>>>(ei);
    finalize_kernel<128, true><<<(NN * 32 + 255) / 256, 256>>>(P(1, 1), P(1, 3), P(1, 4), P(1, 5), P(1, 6));

    // ---- layer 2 (128 -> 64, no relu, + L2 normalize) ----
    gemm_kernel<64, true><<<(NN + 63) / 64, 256, SMEM64>>>(nullptr, P(2, 0), P(2, 2));
    zero_agg_kernel<<<(NN * 16 + 255) / 256, 256>>>(NN * 16);
    scatter_kernel<64><<<(EE * 16 + 255) / 256, 256>>>(ei);
    finalize_norm_kernel<<<(NN * 32 + 255) / 256, 256>>>(P(2, 1), P(2, 3), P(2, 4), P(2, 5), P(2, 6),
                                                         (float*)d_out);
}

// round 2
// speedup vs baseline: 1.1362x; 1.1362x over previous
#include <cuda_runtime.h>

#define NN 50000
#define EE 800000

// ---------------- scratch (static device globals; no allocation) ----------------
__device__ int   g_cnt   [NN];
__device__ int   g_rowptr[NN + 1];
__device__ int   g_cursor[NN];
__device__ int   g_adj   [EE];
__device__ float g_h  [NN * 128];   // layer output ping (reused each layer)
__device__ float g_yl [NN * 128];   // neighbor-linear pre-aggregation
__device__ float g_yr [NN * 128];   // root-linear

// ---------------- CSR build ----------------
__global__ void zero_cnt_kernel() {
    int i = blockIdx.x * blockDim.x + threadIdx.x;
    if (i < NN) g_cnt[i] = 0;
}

__global__ void hist_kernel(const int* __restrict__ ei) {
    int i = blockIdx.x * blockDim.x + threadIdx.x;
    if (i < EE) atomicAdd(&g_cnt[ei[EE + i]], 1);
}

__global__ void __launch_bounds__(1024, 1) scan_kernel() {
    __shared__ int sums[1024];
    const int t  = threadIdx.x;
    const int CH = (NN + 1023) / 1024;   // 49
    const int base = t * CH;
    int s = 0;
    for (int i = 0; i < CH; i++) {
        int idx = base + i;
        if (idx < NN) s += g_cnt[idx];
    }
    sums[t] = s;
    __syncthreads();
    // Hillis-Steele inclusive scan
    for (int off = 1; off < 1024; off <<= 1) {
        int v = (t >= off) ? sums[t - off] : 0;
        __syncthreads();
        sums[t] += v;
        __syncthreads();
    }
    int run = (t == 0) ? 0 : sums[t - 1];
    for (int i = 0; i < CH; i++) {
        int idx = base + i;
        if (idx < NN) {
            g_rowptr[idx] = run;
            g_cursor[idx] = run;
            run += g_cnt[idx];
        }
    }
    if (t == 1023) g_rowptr[NN] = run;
}

__global__ void fill_kernel(const int* __restrict__ ei) {
    int i = blockIdx.x * blockDim.x + threadIdx.x;
    if (i < EE) {
        int s = ei[i];
        int d = ei[EE + i];
        int p = atomicAdd(&g_cursor[d], 1);
        g_adj[p] = s;
    }
}

// ---------------- dual GEMM: y[l|r] = X @ W[l|r]^T ----------------
template <int DOUT, bool USE_H>
__global__ void __launch_bounds__(256, 1)
gemm_kernel(const float* __restrict__ Xext,
            const float* __restrict__ Wl,
            const float* __restrict__ Wr)
{
    constexpr int K  = 128;
    constexpr int D2 = 2 * DOUT;
    constexpr int CG = D2 / 4;        // column groups (4 cols each)
    constexpr int RG = 256 / CG;      // row groups
    constexpr int BM = RG * 8;        // rows per block
    constexpr int WP = D2 + 4;        // Ws pitch (floats)
    constexpr int XP = BM + 4;        // Xs pitch (floats)

    extern __shared__ float sm[];
    float* Ws = sm;              // K * WP
    float* Xs = sm + K * WP;     // K * XP

    const float* X = USE_H ? (const float*)g_h : Xext;

    const int tid  = threadIdx.x;
    const int row0 = blockIdx.x * BM;

    for (int idx = tid; idx < D2 * K; idx += 256) {
        int c = idx / K, k = idx % K;
        float v = (c < DOUT) ? Wl[c * K + k] : Wr[(c - DOUT) * K + k];
        Ws[k * WP + c] = v;
    }
    for (int idx = tid; idx < BM * K; idx += 256) {
        int r = idx / K, k = idx % K;
        int grow = row0 + r;
        Xs[k * XP + r] = (grow < NN) ? X[grow * K + k] : 0.0f;
    }
    __syncthreads();

    const int cg  = tid % CG;
    const int rg  = tid / CG;
    const int col = cg * 4;
    const int rb  = rg * 8;

    float acc[8][4];
#pragma unroll
    for (int r = 0; r < 8; r++)
#pragma unroll
        for (int c = 0; c < 4; c++) acc[r][c] = 0.0f;

#pragma unroll 4
    for (int k = 0; k < K; k++) {
        float4 w  = *(const float4*)&Ws[k * WP + col];
        float4 xa = *(const float4*)&Xs[k * XP + rb];
        float4 xb = *(const float4*)&Xs[k * XP + rb + 4];
        float xr[8] = {xa.x, xa.y, xa.z, xa.w, xb.x, xb.y, xb.z, xb.w};
        float wc[4] = {w.x, w.y, w.z, w.w};
#pragma unroll
        for (int r = 0; r < 8; r++)
#pragma unroll
            for (int c = 0; c < 4; c++)
                acc[r][c] += xr[r] * wc[c];
    }

#pragma unroll
    for (int r = 0; r < 8; r++) {
        int grow = row0 + rb + r;
        if (grow < NN) {
            float4 o = make_float4(acc[r][0], acc[r][1], acc[r][2], acc[r][3]);
            if (col < DOUT)
                *(float4*)&g_yl[grow * DOUT + col] = o;
            else
                *(float4*)&g_yr[grow * DOUT + col - DOUT] = o;
        }
    }
}

// ---------------- fused CSR gather + mean + bias + root + BN (+ReLU) -> g_h ----------------
template <bool RELU>
__global__ void gather_fin128_kernel(const float* __restrict__ bl,
                                     const float* __restrict__ g,
                                     const float* __restrict__ b,
                                     const float* __restrict__ rm,
                                     const float* __restrict__ rv)
{
    int w    = (blockIdx.x * blockDim.x + threadIdx.x) >> 5;
    int lane = threadIdx.x & 31;
    if (w >= NN) return;

    int beg = g_rowptr[w];
    int end = g_rowptr[w + 1];

    const float4* yl4 = (const float4*)g_yl;
    float4 acc = make_float4(0.f, 0.f, 0.f, 0.f);

    for (int base = beg; base < end; base += 32) {
        int n  = min(32, end - base);
        int id = (base + lane < end) ? g_adj[base + lane] : 0;
#pragma unroll 4
        for (int j = 0; j < n; j++) {
            int s = __shfl_sync(0xffffffffu, id, j);
            float4 v = yl4[s * 32 + lane];
            acc.x += v.x; acc.y += v.y; acc.z += v.z; acc.w += v.w;
        }
    }

    float inv = (end > beg) ? 1.0f / (float)(end - beg) : 1.0f;

    float4 BL = ((const float4*)bl)[lane];
    float4 G  = ((const float4*)g )[lane];
    float4 B  = ((const float4*)b )[lane];
    float4 RM = ((const float4*)rm)[lane];
    float4 RV = ((const float4*)rv)[lane];
    float4 y  = ((const float4*)g_yr)[w * 32 + lane];

    float sx = G.x * rsqrtf(RV.x + 1e-5f);
    float sy = G.y * rsqrtf(RV.y + 1e-5f);
    float sz = G.z * rsqrtf(RV.z + 1e-5f);
    float sw = G.w * rsqrtf(RV.w + 1e-5f);

    float4 o;
    o.x = (acc.x * inv + BL.x + y.x - RM.x) * sx + B.x;
    o.y = (acc.y * inv + BL.y + y.y - RM.y) * sy + B.y;
    o.z = (acc.z * inv + BL.z + y.z - RM.z) * sz + B.z;
    o.w = (acc.w * inv + BL.w + y.w - RM.w) * sw + B.w;
    if (RELU) {
        o.x = fmaxf(o.x, 0.f); o.y = fmaxf(o.y, 0.f);
        o.z = fmaxf(o.z, 0.f); o.w = fmaxf(o.w, 0.f);
    }
    ((float4*)g_h)[w * 32 + lane] = o;
}

// ---------------- layer 2: fused gather + finalize + row L2 normalize -> out ----------------
__global__ void gather_fin64_norm_kernel(const float* __restrict__ bl,
                                         const float* __restrict__ g,
                                         const float* __restrict__ b,
                                         const float* __restrict__ rm,
                                         const float* __restrict__ rv,
                                         float* __restrict__ out)
{
    int w    = (blockIdx.x * blockDim.x + threadIdx.x) >> 5;
    int lane = threadIdx.x & 31;
    if (w >= NN) return;

    int beg = g_rowptr[w];
    int end = g_rowptr[w + 1];

    const float2* yl2 = (const float2*)g_yl;
    float2 acc = make_float2(0.f, 0.f);

    for (int base = beg; base < end; base += 32) {
        int n  = min(32, end - base);
        int id = (base + lane < end) ? g_adj[base + lane] : 0;
#pragma unroll 4
        for (int j = 0; j < n; j++) {
            int s = __shfl_sync(0xffffffffu, id, j);
            float2 v = yl2[s * 32 + lane];
            acc.x += v.x; acc.y += v.y;
        }
    }

    float inv = (end > beg) ? 1.0f / (float)(end - beg) : 1.0f;

    float2 BL = ((const float2*)bl)[lane];
    float2 G  = ((const float2*)g )[lane];
    float2 B  = ((const float2*)b )[lane];
    float2 RM = ((const float2*)rm)[lane];
    float2 RV = ((const float2*)rv)[lane];
    float2 y  = ((const float2*)g_yr)[w * 32 + lane];

    float v0 = (acc.x * inv + BL.x + y.x - RM.x) * (G.x * rsqrtf(RV.x + 1e-5f)) + B.x;
    float v1 = (acc.y * inv + BL.y + y.y - RM.y) * (G.y * rsqrtf(RV.y + 1e-5f)) + B.y;

    float s = v0 * v0 + v1 * v1;
#pragma unroll
    for (int off = 16; off > 0; off >>= 1)
        s += __shfl_xor_sync(0xffffffffu, s, off);

    float scale = 1.0f / fmaxf(sqrtf(s), 1e-12f);
    ((float2*)out)[w * 32 + lane] = make_float2(v0 * scale, v1 * scale);
}

// ---------------- launch ----------------
extern "C" void kernel_launch(void* const* d_in, const int* in_sizes, int n_in,
                              void* d_out, int out_size)
{
    const float* x  = (const float*)d_in[0];
    const int*   ei = (const int*)d_in[1];
    auto P = [&](int layer, int j) { return (const float*)d_in[2 + layer * 7 + j]; };
    // j: 0=Wl, 1=bl, 2=Wr, 3=g, 4=b, 5=rm, 6=rv

    const int SMEM128 = (128 * (256 + 4) + 128 * (32 + 4)) * 4;  // 151552
    const int SMEM64  = (128 * (128 + 4) + 128 * (64 + 4)) * 4;  // 102400
    cudaFuncSetAttribute(gemm_kernel<128, false>, cudaFuncAttributeMaxDynamicSharedMemorySize, SMEM128);
    cudaFuncSetAttribute(gemm_kernel<128, true>,  cudaFuncAttributeMaxDynamicSharedMemorySize, SMEM128);
    cudaFuncSetAttribute(gemm_kernel<64,  true>,  cudaFuncAttributeMaxDynamicSharedMemorySize, SMEM64);

    // ---- CSR build (once per call, reused by all layers) ----
    zero_cnt_kernel<<<(NN + 255) / 256, 256>>>();
    hist_kernel<<<(EE + 255) / 256, 256>>>(ei);
    scan_kernel<<<1, 1024>>>();
    fill_kernel<<<(EE + 255) / 256, 256>>>(ei);

    // ---- layer 0 (128 -> 128, relu) ----
    gemm_kernel<128, false><<<(NN + 31) / 32, 256, SMEM128>>>(x, P(0, 0), P(0, 2));
    gather_fin128_kernel<true><<<(NN + 7) / 8, 256>>>(P(0, 1), P(0, 3), P(0, 4), P(0, 5), P(0, 6));

    // ---- layer 1 (128 -> 128, relu) ----
    gemm_kernel<128, true><<<(NN + 31) / 32, 256, SMEM128>>>(nullptr, P(1, 0), P(1, 2));
    gather_fin128_kernel<true><<<(NN + 7) / 8, 256>>>(P(1, 1), P(1, 3), P(1, 4), P(1, 5), P(1, 6));

    // ---- layer 2 (128 -> 64, no relu, + L2 normalize) ----
    gemm_kernel<64, true><<<(NN + 63) / 64, 256, SMEM64>>>(nullptr, P(2, 0), P(2, 2));
    gather_fin64_norm_kernel<<<(NN + 7) / 8, 256>>>(P(2, 1), P(2, 3), P(2, 4), P(2, 5), P(2, 6),
                                                    (float*)d_out);
}

// round 4
// speedup vs baseline: 1.5746x; 1.3858x over previous
#include <cuda_runtime.h>
#include <cstdint>

#define NN 50000
#define EE 800000

// ---------------- scratch (static device globals; no allocation) ----------------
__device__ int   g_cnt   [NN];
__device__ int   g_rowptr[NN + 1];
__device__ int   g_cursor[NN];
__device__ int   g_adj   [EE];
__device__ float g_h  [NN * 128];   // layer output ping (reused each layer)
__device__ float g_yl [NN * 128];   // neighbor-linear pre-aggregation
__device__ float g_yr [NN * 128];   // root-linear

// ---------------- CSR build ----------------
__global__ void zero_cnt_kernel() {
    int i = blockIdx.x * blockDim.x + threadIdx.x;
    if (i < NN) g_cnt[i] = 0;
}

__global__ void hist_kernel(const int* __restrict__ ei) {
    int i = blockIdx.x * blockDim.x + threadIdx.x;
    if (i < EE) atomicAdd(&g_cnt[ei[EE + i]], 1);
}

__global__ void __launch_bounds__(1024, 1) scan_kernel() {
    __shared__ int sums[1024];
    const int t  = threadIdx.x;
    const int CH = (NN + 1023) / 1024;   // 49
    const int base = t * CH;
    int s = 0;
    for (int i = 0; i < CH; i++) {
        int idx = base + i;
        if (idx < NN) s += g_cnt[idx];
    }
    sums[t] = s;
    __syncthreads();
    for (int off = 1; off < 1024; off <<= 1) {
        int v = (t >= off) ? sums[t - off] : 0;
        __syncthreads();
        sums[t] += v;
        __syncthreads();
    }
    int run = (t == 0) ? 0 : sums[t - 1];
    for (int i = 0; i < CH; i++) {
        int idx = base + i;
        if (idx < NN) {
            g_rowptr[idx] = run;
            g_cursor[idx] = run;
            run += g_cnt[idx];
        }
    }
    if (t == 1023) g_rowptr[NN] = run;
}

__global__ void fill_kernel(const int* __restrict__ ei) {
    int i = blockIdx.x * blockDim.x + threadIdx.x;
    if (i < EE) {
        int s = ei[i];
        int d = ei[EE + i];
        int p = atomicAdd(&g_cursor[d], 1);
        g_adj[p] = s;
    }
}

// ---------------- tf32 split-precision helpers ----------------
__device__ __forceinline__ uint32_t f2tf32(float x) {
    uint32_t r;
    asm("cvt.rna.tf32.f32 %0, %1;" : "=r"(r) : "f"(x));
    return r;
}

__device__ __forceinline__ void mma_tf32(float* d, const uint32_t* a, const uint32_t* b) {
    asm volatile(
        "mma.sync.aligned.m16n8k8.row.col.f32.tf32.tf32.f32 "
        "{%0,%1,%2,%3}, {%4,%5,%6,%7}, {%8,%9}, {%0,%1,%2,%3};"
        : "+f"(d[0]), "+f"(d[1]), "+f"(d[2]), "+f"(d[3])
        : "r"(a[0]), "r"(a[1]), "r"(a[2]), "r"(a[3]), "r"(b[0]), "r"(b[1]));
}

// ---------------- tf32 mma.sync dual GEMM: [yl|yr] = X @ [Wl|Wr]^T ----------------
// Block tile: BM=128 rows x 64 cols. grid = (NT, D2/64).
// 8 warps: 4 (M) x 2 (N), each warp computes 32x32 via m16n8k8.
// Split precision: X = Xhi + Xlo, W = Whi + Wlo (tf32 each);
// acc += AhiBhi + AloBhi + AhiBlo  (error ~2^-22).
template <int DOUT, bool USE_H>
__global__ void __launch_bounds__(256, 1)
tc_gemm_kernel(const float* __restrict__ Xext,
               const float* __restrict__ Wl,
               const float* __restrict__ Wr)
{
    constexpr int K  = 128;
    constexpr int P  = 132;                 // smem pitch (floats): bank = 4r+c, conflict-free
    constexpr int XHI = 0;
    constexpr int XLO = 128 * P;
    constexpr int WHI = 2 * 128 * P;
    constexpr int WLO = 2 * 128 * P + 64 * P;
    // total floats = 2*128*132 + 2*64*132 = 50688 -> 202752 bytes

    extern __shared__ float sm[];

    const float* X = USE_H ? (const float*)g_h : Xext;

    const int tid   = threadIdx.x;
    const int lane  = tid & 31;
    const int wid   = tid >> 5;
    const int mwarp = wid & 3;              // 0..3
    const int nwarp = wid >> 2;             // 0..1
    const int row0  = blockIdx.x * 128;
    const int col0  = blockIdx.y * 64;      // within [0, 2*DOUT)

    // ---- stage X tile (128 x 128) as hi/lo ----
    for (int idx = tid; idx < 128 * 32; idx += 256) {
        int r = idx >> 5, kc = idx & 31;
        int grow = row0 + r;
        float4 v = make_float4(0.f, 0.f, 0.f, 0.f);
        if (grow < NN) v = *(const float4*)(X + grow * K + kc * 4);
        float hx = __uint_as_float(f2tf32(v.x));
        float hy = __uint_as_float(f2tf32(v.y));
        float hz = __uint_as_float(f2tf32(v.z));
        float hw = __uint_as_float(f2tf32(v.w));
        sm[XHI + r * P + kc * 4 + 0] = hx;
        sm[XHI + r * P + kc * 4 + 1] = hy;
        sm[XHI + r * P + kc * 4 + 2] = hz;
        sm[XHI + r * P + kc * 4 + 3] = hw;
        sm[XLO + r * P + kc * 4 + 0] = __uint_as_float(f2tf32(v.x - hx));
        sm[XLO + r * P + kc * 4 + 1] = __uint_as_float(f2tf32(v.y - hy));
        sm[XLO + r * P + kc * 4 + 2] = __uint_as_float(f2tf32(v.z - hz));
        sm[XLO + r * P + kc * 4 + 3] = __uint_as_float(f2tf32(v.w - hw));
    }
    // ---- stage W tile (64 x 128) as hi/lo ----
    for (int idx = tid; idx < 64 * 32; idx += 256) {
        int r = idx >> 5, kc = idx & 31;
        int gc = col0 + r;
        const float* src = (gc < DOUT) ? (Wl + gc * K) : (Wr + (gc - DOUT) * K);
        float4 v = *(const float4*)(src + kc * 4);
        float hx = __uint_as_float(f2tf32(v.x));
        float hy = __uint_as_float(f2tf32(v.y));
        float hz = __uint_as_float(f2tf32(v.z));
        float hw = __uint_as_float(f2tf32(v.w));
        sm[WHI + r * P + kc * 4 + 0] = hx;
        sm[WHI + r * P + kc * 4 + 1] = hy;
        sm[WHI + r * P + kc * 4 + 2] = hz;
        sm[WHI + r * P + kc * 4 + 3] = hw;
        sm[WLO + r * P + kc * 4 + 0] = __uint_as_float(f2tf32(v.x - hx));
        sm[WLO + r * P + kc * 4 + 1] = __uint_as_float(f2tf32(v.y - hy));
        sm[WLO + r * P + kc * 4 + 2] = __uint_as_float(f2tf32(v.z - hz));
        sm[WLO + r * P + kc * 4 + 3] = __uint_as_float(f2tf32(v.w - hw));
    }
    __syncthreads();

    const int r = lane >> 2;     // group id 0..7
    const int c = lane & 3;      // thread-in-group 0..3

    float acc[2][4][4];
#pragma unroll
    for (int mt = 0; mt < 2; mt++)
#pragma unroll
        for (int nt = 0; nt < 4; nt++)
#pragma unroll
            for (int j = 0; j < 4; j++) acc[mt][nt][j] = 0.f;

    for (int kt = 0; kt < 16; kt++) {
        const int k0 = kt * 8;
        uint32_t ahi[2][4], alo[2][4];
#pragma unroll
        for (int mt = 0; mt < 2; mt++) {
            int rb = mwarp * 32 + mt * 16;
            ahi[mt][0] = __float_as_uint(sm[XHI + (rb + r)     * P + k0 + c]);
            ahi[mt][1] = __float_as_uint(sm[XHI + (rb + r + 8) * P + k0 + c]);
            ahi[mt][2] = __float_as_uint(sm[XHI + (rb + r)     * P + k0 + c + 4]);
            ahi[mt][3] = __float_as_uint(sm[XHI + (rb + r + 8) * P + k0 + c + 4]);
            alo[mt][0] = __float_as_uint(sm[XLO + (rb + r)     * P + k0 + c]);
            alo[mt][1] = __float_as_uint(sm[XLO + (rb + r + 8) * P + k0 + c]);
            alo[mt][2] = __float_as_uint(sm[XLO + (rb + r)     * P + k0 + c + 4]);
            alo[mt][3] = __float_as_uint(sm[XLO + (rb + r + 8) * P + k0 + c + 4]);
        }
        uint32_t bhi[4][2], blo[4][2];
#pragma unroll
        for (int nt = 0; nt < 4; nt++) {
            int cb = nwarp * 32 + nt * 8 + r;
            bhi[nt][0] = __float_as_uint(sm[WHI + cb * P + k0 + c]);
            bhi[nt][1] = __float_as_uint(sm[WHI + cb * P + k0 + c + 4]);
            blo[nt][0] = __float_as_uint(sm[WLO + cb * P + k0 + c]);
            blo[nt][1] = __float_as_uint(sm[WLO + cb * P + k0 + c + 4]);
        }
#pragma unroll
        for (int mt = 0; mt < 2; mt++)
#pragma unroll
            for (int nt = 0; nt < 4; nt++) {
                mma_tf32(acc[mt][nt], ahi[mt], bhi[nt]);
                mma_tf32(acc[mt][nt], alo[mt], bhi[nt]);
                mma_tf32(acc[mt][nt], ahi[mt], blo[nt]);
            }
    }

    // ---- epilogue: scatter accumulators to g_yl / g_yr ----
#pragma unroll
    for (int mt = 0; mt < 2; mt++) {
        int rowg0 = row0 + mwarp * 32 + mt * 16 + r;
#pragma unroll
        for (int nt = 0; nt < 4; nt++) {
            int colq = col0 + nwarp * 32 + nt * 8 + 2 * c;   // within D2
            float* dstbase;
            int col;
            if (colq < DOUT) { dstbase = g_yl; col = colq; }
            else             { dstbase = g_yr; col = colq - DOUT; }
            if (rowg0 < NN)
                *(float2*)(dstbase + rowg0 * DOUT + col)
                    = make_float2(acc[mt][nt][0], acc[mt][nt][1]);
            if (rowg0 + 8 < NN)
                *(float2*)(dstbase + (rowg0 + 8) * DOUT + col)
                    = make_float2(acc[mt][nt][2], acc[mt][nt][3]);
        }
    }
}

// ---------------- fused CSR gather + mean + bias + root + BN (+ReLU) -> g_h ----------------
template <bool RELU>
__global__ void gather_fin128_kernel(const float* __restrict__ bl,
                                     const float* __restrict__ g,
                                     const float* __restrict__ b,
                                     const float* __restrict__ rm,
                                     const float* __restrict__ rv)
{
    int w    = (blockIdx.x * blockDim.x + threadIdx.x) >> 5;
    int lane = threadIdx.x & 31;
    if (w >= NN) return;

    int beg = g_rowptr[w];
    int end = g_rowptr[w + 1];

    const float4* yl4 = (const float4*)g_yl;
    float4 acc = make_float4(0.f, 0.f, 0.f, 0.f);

    for (int base = beg; base < end; base += 32) {
        int n  = min(32, end - base);
        int id = (base + lane < end) ? g_adj[base + lane] : 0;
#pragma unroll 4
        for (int j = 0; j < n; j++) {
            int s = __shfl_sync(0xffffffffu, id, j);
            float4 v = yl4[s * 32 + lane];
            acc.x += v.x; acc.y += v.y; acc.z += v.z; acc.w += v.w;
        }
    }

    float inv = (end > beg) ? 1.0f / (float)(end - beg) : 1.0f;

    float4 BL = ((const float4*)bl)[lane];
    float4 G  = ((const float4*)g )[lane];
    float4 B  = ((const float4*)b )[lane];
    float4 RM = ((const float4*)rm)[lane];
    float4 RV = ((const float4*)rv)[lane];
    float4 y  = ((const float4*)g_yr)[w * 32 + lane];

    float sx = G.x * rsqrtf(RV.x + 1e-5f);
    float sy = G.y * rsqrtf(RV.y + 1e-5f);
    float sz = G.z * rsqrtf(RV.z + 1e-5f);
    float sw = G.w * rsqrtf(RV.w + 1e-5f);

    float4 o;
    o.x = (acc.x * inv + BL.x + y.x - RM.x) * sx + B.x;
    o.y = (acc.y * inv + BL.y + y.y - RM.y) * sy + B.y;
    o.z = (acc.z * inv + BL.z + y.z - RM.z) * sz + B.z;
    o.w = (acc.w * inv + BL.w + y.w - RM.w) * sw + B.w;
    if (RELU) {
        o.x = fmaxf(o.x, 0.f); o.y = fmaxf(o.y, 0.f);
        o.z = fmaxf(o.z, 0.f); o.w = fmaxf(o.w, 0.f);
    }
    ((float4*)g_h)[w * 32 + lane] = o;
}

// ---------------- layer 2: fused gather + finalize + row L2 normalize -> out ----------------
__global__ void gather_fin64_norm_kernel(const float* __restrict__ bl,
                                         const float* __restrict__ g,
                                         const float* __restrict__ b,
                                         const float* __restrict__ rm,
                                         const float* __restrict__ rv,
                                         float* __restrict__ out)
{
    int w    = (blockIdx.x * blockDim.x + threadIdx.x) >> 5;
    int lane = threadIdx.x & 31;
    if (w >= NN) return;

    int beg = g_rowptr[w];
    int end = g_rowptr[w + 1];

    const float2* yl2 = (const float2*)g_yl;
    float2 acc = make_float2(0.f, 0.f);

    for (int base = beg; base < end; base += 32) {
        int n  = min(32, end - base);
        int id = (base + lane < end) ? g_adj[base + lane] : 0;
#pragma unroll 4
        for (int j = 0; j < n; j++) {
            int s = __shfl_sync(0xffffffffu, id, j);
            float2 v = yl2[s * 32 + lane];
            acc.x += v.x; acc.y += v.y;
        }
    }

    float inv = (end > beg) ? 1.0f / (float)(end - beg) : 1.0f;

    float2 BL = ((const float2*)bl)[lane];
    float2 G  = ((const float2*)g )[lane];
    float2 B  = ((const float2*)b )[lane];
    float2 RM = ((const float2*)rm)[lane];
    float2 RV = ((const float2*)rv)[lane];
    float2 y  = ((const float2*)g_yr)[w * 32 + lane];

    float v0 = (acc.x * inv + BL.x + y.x - RM.x) * (G.x * rsqrtf(RV.x + 1e-5f)) + B.x;
    float v1 = (acc.y * inv + BL.y + y.y - RM.y) * (G.y * rsqrtf(RV.y + 1e-5f)) + B.y;

    float s = v0 * v0 + v1 * v1;
#pragma unroll
    for (int off = 16; off > 0; off >>= 1)
        s += __shfl_xor_sync(0xffffffffu, s, off);

    float scale = 1.0f / fmaxf(sqrtf(s), 1e-12f);
    ((float2*)out)[w * 32 + lane] = make_float2(v0 * scale, v1 * scale);
}

// ---------------- launch ----------------
extern "C" void kernel_launch(void* const* d_in, const int* in_sizes, int n_in,
                              void* d_out, int out_size)
{
    const float* x  = (const float*)d_in[0];
    const int*   ei = (const int*)d_in[1];
    auto P = [&](int layer, int j) { return (const float*)d_in[2 + layer * 7 + j]; };
    // j: 0=Wl, 1=bl, 2=Wr, 3=g, 4=b, 5=rm, 6=rv

    const int SMEM = (2 * 128 * 132 + 2 * 64 * 132) * 4;  // 202752 bytes
    cudaFuncSetAttribute(tc_gemm_kernel<128, false>, cudaFuncAttributeMaxDynamicSharedMemorySize, SMEM);
    cudaFuncSetAttribute(tc_gemm_kernel<128, true>,  cudaFuncAttributeMaxDynamicSharedMemorySize, SMEM);
    cudaFuncSetAttribute(tc_gemm_kernel<64,  true>,  cudaFuncAttributeMaxDynamicSharedMemorySize, SMEM);

    const int NT = (NN + 127) / 128;   // 391 M-tiles

    // ---- CSR build (once per call, reused by all layers) ----
    zero_cnt_kernel<<<(NN + 255) / 256, 256>>>();
    hist_kernel<<<(EE + 255) / 256, 256>>>(ei);
    scan_kernel<<<1, 1024>>>();
    fill_kernel<<<(EE + 255) / 256, 256>>>(ei);

    // ---- layer 0 (128 -> 128, relu) ----
    tc_gemm_kernel<128, false><<<dim3(NT, 4), 256, SMEM>>>(x, P(0, 0), P(0, 2));
    gather_fin128_kernel<true><<<(NN + 7) / 8, 256>>>(P(0, 1), P(0, 3), P(0, 4), P(0, 5), P(0, 6));

    // ---- layer 1 (128 -> 128, relu) ----
    tc_gemm_kernel<128, true><<<dim3(NT, 4), 256, SMEM>>>(nullptr, P(1, 0), P(1, 2));
    gather_fin128_kernel<true><<<(NN + 7) / 8, 256>>>(P(1, 1), P(1, 3), P(1, 4), P(1, 5), P(1, 6));

    // ---- layer 2 (128 -> 64, no relu, + L2 normalize) ----
    tc_gemm_kernel<64, true><<<dim3(NT, 2), 256, SMEM>>>(nullptr, P(2, 0), P(2, 2));
    gather_fin64_norm_kernel<<<(NN + 7) / 8, 256>>>(P(2, 1), P(2, 3), P(2, 4), P(2, 5), P(2, 6),
                                                    (float*)d_out);
}

// round 5
// speedup vs baseline: 1.9947x; 1.2668x over previous
#include <cuda_runtime.h>
#include <cstdint>

#define NN 50000
#define EE 800000

// ---------------- scratch (static device globals; no allocation) ----------------
__device__ int   g_cnt   [NN];
__device__ int   g_rowptr[NN + 1];
__device__ int   g_cursor[NN];
__device__ int   g_adj   [EE];
__device__ float g_h  [NN * 128];   // layer output ping (reused each layer)
__device__ float g_yl [NN * 128];   // neighbor-linear pre-aggregation
__device__ float g_yr [NN * 128];   // root-linear

// ---------------- CSR build ----------------
__global__ void zero_cnt_kernel() {
    int i = blockIdx.x * blockDim.x + threadIdx.x;
    if (i < NN) g_cnt[i] = 0;
}

__global__ void hist_kernel(const int* __restrict__ ei) {
    int i = blockIdx.x * blockDim.x + threadIdx.x;
    if (i < EE) atomicAdd(&g_cnt[ei[EE + i]], 1);
}

__global__ void __launch_bounds__(1024, 1) scan_kernel() {
    __shared__ int sums[1024];
    const int t  = threadIdx.x;
    const int CH = (NN + 1023) / 1024;   // 49
    const int base = t * CH;
    int s = 0;
    for (int i = 0; i < CH; i++) {
        int idx = base + i;
        if (idx < NN) s += g_cnt[idx];
    }
    sums[t] = s;
    __syncthreads();
    for (int off = 1; off < 1024; off <<= 1) {
        int v = (t >= off) ? sums[t - off] : 0;
        __syncthreads();
        sums[t] += v;
        __syncthreads();
    }
    int run = (t == 0) ? 0 : sums[t - 1];
    for (int i = 0; i < CH; i++) {
        int idx = base + i;
        if (idx < NN) {
            g_rowptr[idx] = run;
            g_cursor[idx] = run;
            run += g_cnt[idx];
        }
    }
    if (t == 1023) g_rowptr[NN] = run;
}

__global__ void fill_kernel(const int* __restrict__ ei) {
    int i = blockIdx.x * blockDim.x + threadIdx.x;
    if (i < EE) {
        int s = ei[i];
        int d = ei[EE + i];
        int p = atomicAdd(&g_cursor[d], 1);
        g_adj[p] = s;
    }
}

// ---------------- tf32 split-precision helpers ----------------
__device__ __forceinline__ uint32_t f2tf32(float x) {
    uint32_t r;
    asm("cvt.rna.tf32.f32 %0, %1;" : "=r"(r) : "f"(x));
    return r;
}

__device__ __forceinline__ void split_tf32(float v, uint32_t& hi, uint32_t& lo) {
    hi = f2tf32(v);
    lo = f2tf32(v - __uint_as_float(hi));
}

__device__ __forceinline__ void mma_tf32(float* d, const uint32_t* a, const uint32_t* b) {
    asm volatile(
        "mma.sync.aligned.m16n8k8.row.col.f32.tf32.tf32.f32 "
        "{%0,%1,%2,%3}, {%4,%5,%6,%7}, {%8,%9}, {%0,%1,%2,%3};"
        : "+f"(d[0]), "+f"(d[1]), "+f"(d[2]), "+f"(d[3])
        : "r"(a[0]), "r"(a[1]), "r"(a[2]), "r"(a[3]), "r"(b[0]), "r"(b[1]));
}

// ---------------- tf32 mma.sync dual GEMM: [yl|yr] = X @ [Wl|Wr]^T ----------------
// Block tile: BM=128 rows x 64 cols. grid = (NT, D2/64).
// 8 warps: 4 (M) x 2 (N), each warp computes 32x32 via m16n8k8.
// Raw f32 staged ONCE in SMEM (101KB -> 2 CTAs/SM); tf32 hi/lo split done in
// registers. acc += AhiBhi + AloBhi + AhiBlo  (error ~2^-22).
template <int DOUT, bool USE_H>
__global__ void __launch_bounds__(256, 2)
tc_gemm_kernel(const float* __restrict__ Xext,
               const float* __restrict__ Wl,
               const float* __restrict__ Wr)
{
    constexpr int K  = 128;
    constexpr int P  = 132;                 // smem pitch (floats): bank = 4r+c, conflict-free
    constexpr int XS = 0;
    constexpr int WS = 128 * P;
    // total floats = 128*132 + 64*132 = 25344 -> 101376 bytes

    extern __shared__ float sm[];

    const float* X = USE_H ? (const float*)g_h : Xext;

    const int tid   = threadIdx.x;
    const int lane  = tid & 31;
    const int wid   = tid >> 5;
    const int mwarp = wid & 3;              // 0..3
    const int nwarp = wid >> 2;             // 0..1
    const int row0  = blockIdx.x * 128;
    const int col0  = blockIdx.y * 64;      // within [0, 2*DOUT)

    // ---- stage X tile (128 x 128) raw ----
    for (int idx = tid; idx < 128 * 32; idx += 256) {
        int r = idx >> 5, kc = idx & 31;
        int grow = row0 + r;
        float4 v = make_float4(0.f, 0.f, 0.f, 0.f);
        if (grow < NN) v = *(const float4*)(X + grow * K + kc * 4);
        *(float4*)&sm[XS + r * P + kc * 4] = v;
    }
    // ---- stage W tile (64 x 128) raw ----
    for (int idx = tid; idx < 64 * 32; idx += 256) {
        int r = idx >> 5, kc = idx & 31;
        int gc = col0 + r;
        const float* src = (gc < DOUT) ? (Wl + gc * K) : (Wr + (gc - DOUT) * K);
        *(float4*)&sm[WS + r * P + kc * 4] = *(const float4*)(src + kc * 4);
    }
    __syncthreads();

    const int r = lane >> 2;     // group id 0..7
    const int c = lane & 3;      // thread-in-group 0..3

    float acc[2][4][4];
#pragma unroll
    for (int mt = 0; mt < 2; mt++)
#pragma unroll
        for (int nt = 0; nt < 4; nt++)
#pragma unroll
            for (int j = 0; j < 4; j++) acc[mt][nt][j] = 0.f;

#pragma unroll 2
    for (int kt = 0; kt < 16; kt++) {
        const int k0 = kt * 8;
        uint32_t ahi[2][4], alo[2][4];
#pragma unroll
        for (int mt = 0; mt < 2; mt++) {
            int rb = mwarp * 32 + mt * 16;
            float a0 = sm[XS + (rb + r)     * P + k0 + c];
            float a1 = sm[XS + (rb + r + 8) * P + k0 + c];
            float a2 = sm[XS + (rb + r)     * P + k0 + c + 4];
            float a3 = sm[XS + (rb + r + 8) * P + k0 + c + 4];
            split_tf32(a0, ahi[mt][0], alo[mt][0]);
            split_tf32(a1, ahi[mt][1], alo[mt][1]);
            split_tf32(a2, ahi[mt][2], alo[mt][2]);
            split_tf32(a3, ahi[mt][3], alo[mt][3]);
        }
        uint32_t bhi[4][2], blo[4][2];
#pragma unroll
        for (int nt = 0; nt < 4; nt++) {
            int cb = nwarp * 32 + nt * 8 + r;
            float b0 = sm[WS + cb * P + k0 + c];
            float b1 = sm[WS + cb * P + k0 + c + 4];
            split_tf32(b0, bhi[nt][0], blo[nt][0]);
            split_tf32(b1, bhi[nt][1], blo[nt][1]);
        }
#pragma unroll
        for (int mt = 0; mt < 2; mt++)
#pragma unroll
            for (int nt = 0; nt < 4; nt++) {
                mma_tf32(acc[mt][nt], ahi[mt], bhi[nt]);
                mma_tf32(acc[mt][nt], alo[mt], bhi[nt]);
                mma_tf32(acc[mt][nt], ahi[mt], blo[nt]);
            }
    }

    // ---- epilogue: scatter accumulators to g_yl / g_yr ----
#pragma unroll
    for (int mt = 0; mt < 2; mt++) {
        int rowg0 = row0 + mwarp * 32 + mt * 16 + r;
#pragma unroll
        for (int nt = 0; nt < 4; nt++) {
            int colq = col0 + nwarp * 32 + nt * 8 + 2 * c;   // within D2
            float* dstbase;
            int col;
            if (colq < DOUT) { dstbase = g_yl; col = colq; }
            else             { dstbase = g_yr; col = colq - DOUT; }
            if (rowg0 < NN)
                *(float2*)(dstbase + rowg0 * DOUT + col)
                    = make_float2(acc[mt][nt][0], acc[mt][nt][1]);
            if (rowg0 + 8 < NN)
                *(float2*)(dstbase + (rowg0 + 8) * DOUT + col)
                    = make_float2(acc[mt][nt][2], acc[mt][nt][3]);
        }
    }
}

// ---------------- fused CSR gather + mean + bias + root + BN (+ReLU) -> g_h ----------------
template <bool RELU>
__global__ void gather_fin128_kernel(const float* __restrict__ bl,
                                     const float* __restrict__ g,
                                     const float* __restrict__ b,
                                     const float* __restrict__ rm,
                                     const float* __restrict__ rv)
{
    int w    = (blockIdx.x * blockDim.x + threadIdx.x) >> 5;
    int lane = threadIdx.x & 31;
    if (w >= NN) return;

    int beg = g_rowptr[w];
    int end = g_rowptr[w + 1];

    const float4* yl4 = (const float4*)g_yl;
    float4 acc = make_float4(0.f, 0.f, 0.f, 0.f);

    for (int base = beg; base < end; base += 32) {
        int n  = min(32, end - base);
        int id = (base + lane < end) ? g_adj[base + lane] : 0;
#pragma unroll 4
        for (int j = 0; j < n; j++) {
            int s = __shfl_sync(0xffffffffu, id, j);
            float4 v = yl4[s * 32 + lane];
            acc.x += v.x; acc.y += v.y; acc.z += v.z; acc.w += v.w;
        }
    }

    float inv = (end > beg) ? 1.0f / (float)(end - beg) : 1.0f;

    float4 BL = ((const float4*)bl)[lane];
    float4 G  = ((const float4*)g )[lane];
    float4 B  = ((const float4*)b )[lane];
    float4 RM = ((const float4*)rm)[lane];
    float4 RV = ((const float4*)rv)[lane];
    float4 y  = ((const float4*)g_yr)[w * 32 + lane];

    float sx = G.x * rsqrtf(RV.x + 1e-5f);
    float sy = G.y * rsqrtf(RV.y + 1e-5f);
    float sz = G.z * rsqrtf(RV.z + 1e-5f);
    float sw = G.w * rsqrtf(RV.w + 1e-5f);

    float4 o;
    o.x = (acc.x * inv + BL.x + y.x - RM.x) * sx + B.x;
    o.y = (acc.y * inv + BL.y + y.y - RM.y) * sy + B.y;
    o.z = (acc.z * inv + BL.z + y.z - RM.z) * sz + B.z;
    o.w = (acc.w * inv + BL.w + y.w - RM.w) * sw + B.w;
    if (RELU) {
        o.x = fmaxf(o.x, 0.f); o.y = fmaxf(o.y, 0.f);
        o.z = fmaxf(o.z, 0.f); o.w = fmaxf(o.w, 0.f);
    }
    ((float4*)g_h)[w * 32 + lane] = o;
}

// ---------------- layer 2: fused gather + finalize + row L2 normalize -> out ----------------
__global__ void gather_fin64_norm_kernel(const float* __restrict__ bl,
                                         const float* __restrict__ g,
                                         const float* __restrict__ b,
                                         const float* __restrict__ rm,
                                         const float* __restrict__ rv,
                                         float* __restrict__ out)
{
    int w    = (blockIdx.x * blockDim.x + threadIdx.x) >> 5;
    int lane = threadIdx.x & 31;
    if (w >= NN) return;

    int beg = g_rowptr[w];
    int end = g_rowptr[w + 1];

    const float2* yl2 = (const float2*)g_yl;
    float2 acc = make_float2(0.f, 0.f);

    for (int base = beg; base < end; base += 32) {
        int n  = min(32, end - base);
        int id = (base + lane < end) ? g_adj[base + lane] : 0;
#pragma unroll 4
        for (int j = 0; j < n; j++) {
            int s = __shfl_sync(0xffffffffu, id, j);
            float2 v = yl2[s * 32 + lane];
            acc.x += v.x; acc.y += v.y;
        }
    }

    float inv = (end > beg) ? 1.0f / (float)(end - beg) : 1.0f;

    float2 BL = ((const float2*)bl)[lane];
    float2 G  = ((const float2*)g )[lane];
    float2 B  = ((const float2*)b )[lane];
    float2 RM = ((const float2*)rm)[lane];
    float2 RV = ((const float2*)rv)[lane];
    float2 y  = ((const float2*)g_yr)[w * 32 + lane];

    float v0 = (acc.x * inv + BL.x + y.x - RM.x) * (G.x * rsqrtf(RV.x + 1e-5f)) + B.x;
    float v1 = (acc.y * inv + BL.y + y.y - RM.y) * (G.y * rsqrtf(RV.y + 1e-5f)) + B.y;

    float s = v0 * v0 + v1 * v1;
#pragma unroll
    for (int off = 16; off > 0; off >>= 1)
        s += __shfl_xor_sync(0xffffffffu, s, off);

    float scale = 1.0f / fmaxf(sqrtf(s), 1e-12f);
    ((float2*)out)[w * 32 + lane] = make_float2(v0 * scale, v1 * scale);
}

// ---------------- launch ----------------
extern "C" void kernel_launch(void* const* d_in, const int* in_sizes, int n_in,
                              void* d_out, int out_size)
{
    const float* x  = (const float*)d_in[0];
    const int*   ei = (const int*)d_in[1];
    auto P = [&](int layer, int j) { return (const float*)d_in[2 + layer * 7 + j]; };
    // j: 0=Wl, 1=bl, 2=Wr, 3=g, 4=b, 5=rm, 6=rv

    const int SMEM = (128 * 132 + 64 * 132) * 4;  // 101376 bytes -> 2 CTAs/SM
    cudaFuncSetAttribute(tc_gemm_kernel<128, false>, cudaFuncAttributeMaxDynamicSharedMemorySize, SMEM);
    cudaFuncSetAttribute(tc_gemm_kernel<128, true>,  cudaFuncAttributeMaxDynamicSharedMemorySize, SMEM);
    cudaFuncSetAttribute(tc_gemm_kernel<64,  true>,  cudaFuncAttributeMaxDynamicSharedMemorySize, SMEM);

    const int NT = (NN + 127) / 128;   // 391 M-tiles

    // ---- CSR build (once per call, reused by all layers) ----
    zero_cnt_kernel<<<(NN + 255) / 256, 256>>>();
    hist_kernel<<<(EE + 255) / 256, 256>>>(ei);
    scan_kernel<<<1, 1024>>>();
    fill_kernel<<<(EE + 255) / 256, 256>>>(ei);

    // ---- layer 0 (128 -> 128, relu) ----
    tc_gemm_kernel<128, false><<<dim3(NT, 4), 256, SMEM>>>(x, P(0, 0), P(0, 2));
    gather_fin128_kernel<true><<<(NN + 7) / 8, 256>>>(P(0, 1), P(0, 3), P(0, 4), P(0, 5), P(0, 6));

    // ---- layer 1 (128 -> 128, relu) ----
    tc_gemm_kernel<128, true><<<dim3(NT, 4), 256, SMEM>>>(nullptr, P(1, 0), P(1, 2));
    gather_fin128_kernel<true><<<(NN + 7) / 8, 256>>>(P(1, 1), P(1, 3), P(1, 4), P(1, 5), P(1, 6));

    // ---- layer 2 (128 -> 64, no relu, + L2 normalize) ----
    tc_gemm_kernel<64, true><<<dim3(NT, 2), 256, SMEM>>>(nullptr, P(2, 0), P(2, 2));
    gather_fin64_norm_kernel<<<(NN + 7) / 8, 256>>>(P(2, 1), P(2, 3), P(2, 4), P(2, 5), P(2, 6),
                                                    (float*)d_out);
}

// round 6
// speedup vs baseline: 2.2955x; 1.1508x over previous
#include <cuda_runtime.h>
#include <cuda_bf16.h>
#include <cstdint>

#define NN 50000
#define EE 800000

// ---------------- scratch (static device globals; no allocation) ----------------
__device__ int   g_cnt   [NN];
__device__ int   g_rowptr[NN + 1];
__device__ int   g_cursor[NN];
__device__ int   g_adj   [EE];
__device__ float g_h  [NN * 128];   // layer output ping (reused each layer)
__device__ float g_yl [NN * 128];   // neighbor-linear pre-aggregation
__device__ float g_yr [NN * 128];   // root-linear

// ---------------- CSR build ----------------
__global__ void zero_cnt_kernel() {
    int i = blockIdx.x * blockDim.x + threadIdx.x;
    if (i < NN) g_cnt[i] = 0;
}

__global__ void hist_kernel(const int* __restrict__ ei) {
    int i = blockIdx.x * blockDim.x + threadIdx.x;
    if (i < EE) atomicAdd(&g_cnt[ei[EE + i]], 1);
}

__global__ void __launch_bounds__(1024, 1) scan_kernel() {
    __shared__ int sums[1024];
    const int t  = threadIdx.x;
    const int CH = (NN + 1023) / 1024;   // 49
    const int base = t * CH;
    int s = 0;
    for (int i = 0; i < CH; i++) {
        int idx = base + i;
        if (idx < NN) s += g_cnt[idx];
    }
    sums[t] = s;
    __syncthreads();
    for (int off = 1; off < 1024; off <<= 1) {
        int v = (t >= off) ? sums[t - off] : 0;
        __syncthreads();
        sums[t] += v;
        __syncthreads();
    }
    int run = (t == 0) ? 0 : sums[t - 1];
    for (int i = 0; i < CH; i++) {
        int idx = base + i;
        if (idx < NN) {
            g_rowptr[idx] = run;
            g_cursor[idx] = run;
            run += g_cnt[idx];
        }
    }
    if (t == 1023) g_rowptr[NN] = run;
}

__global__ void fill_kernel(const int* __restrict__ ei) {
    int i = blockIdx.x * blockDim.x + threadIdx.x;
    if (i < EE) {
        int s = ei[i];
        int d = ei[EE + i];
        int p = atomicAdd(&g_cursor[d], 1);
        g_adj[p] = s;
    }
}

// ---------------- bf16 double-split helpers ----------------
// v (f32 pair) -> hi bf16x2 + lo bf16x2 with v ~= hi + lo (|err| ~ 2^-18 |v|)
__device__ __forceinline__ void split_bf16x2(float v0, float v1,
                                             uint32_t& hi, uint32_t& lo) {
    __nv_bfloat162 h = __floats2bfloat162_rn(v0, v1);
    float2 hf = __bfloat1622float2(h);
    __nv_bfloat162 l = __floats2bfloat162_rn(v0 - hf.x, v1 - hf.y);
    hi = *reinterpret_cast<uint32_t*>(&h);
    lo = *reinterpret_cast<uint32_t*>(&l);
}

__device__ __forceinline__ void mma_bf16(float* d, const uint32_t* a, const uint32_t* b) {
    asm volatile(
        "mma.sync.aligned.m16n8k16.row.col.f32.bf16.bf16.f32 "
        "{%0,%1,%2,%3}, {%4,%5,%6,%7}, {%8,%9}, {%0,%1,%2,%3};"
        : "+f"(d[0]), "+f"(d[1]), "+f"(d[2]), "+f"(d[3])
        : "r"(a[0]), "r"(a[1]), "r"(a[2]), "r"(a[3]), "r"(b[0]), "r"(b[1]));
}

// ---------------- bf16 split mma.sync dual GEMM: [yl|yr] = X @ [Wl|Wr]^T ----------------
// Block tile: BM=128 rows x 64 cols. grid = (NT, D2/64).
// 8 warps: 4 (M) x 2 (N), each warp computes 32x32 via m16n8k16.
// hi/lo split computed ONCE at staging, stored packed bf16x2 in SMEM (102KB -> 2 CTAs/SM).
// acc += AhiBhi + AloBhi + AhiBlo  (drops lo*lo ~ 2^-18).
template <int DOUT, bool USE_H>
__global__ void __launch_bounds__(256, 2)
tc_gemm_kernel(const float* __restrict__ Xext,
               const float* __restrict__ Wl,
               const float* __restrict__ Wr)
{
    constexpr int K   = 128;
    constexpr int PP  = 68;                 // pitch in u32 (bf16 pairs); bank = 4r+c
    constexpr int XHI = 0;
    constexpr int XLO = 128 * PP;           // 8704
    constexpr int WHI = 2 * 128 * PP;       // 17408
    constexpr int WLO = 2 * 128 * PP + 64 * PP;   // 21760
    // total u32 = 26112 -> 104448 bytes

    extern __shared__ uint32_t sm[];

    const float* X = USE_H ? (const float*)g_h : Xext;

    const int tid   = threadIdx.x;
    const int lane  = tid & 31;
    const int wid   = tid >> 5;
    const int mwarp = wid & 3;              // 0..3
    const int nwarp = wid >> 2;             // 0..1
    const int row0  = blockIdx.x * 128;
    const int col0  = blockIdx.y * 64;      // within [0, 2*DOUT)

    // ---- stage X tile (128 x 128 f32) split into bf16x2 hi/lo ----
    for (int idx = tid; idx < 128 * 32; idx += 256) {
        int r = idx >> 5, q = idx & 31;     // q = float4 index (2 pairs)
        int grow = row0 + r;
        float4 v = make_float4(0.f, 0.f, 0.f, 0.f);
        if (grow < NN) v = *(const float4*)(X + grow * K + q * 4);
        uint32_t h0, l0, h1, l1;
        split_bf16x2(v.x, v.y, h0, l0);
        split_bf16x2(v.z, v.w, h1, l1);
        sm[XHI + r * PP + q * 2]     = h0;
        sm[XHI + r * PP + q * 2 + 1] = h1;
        sm[XLO + r * PP + q * 2]     = l0;
        sm[XLO + r * PP + q * 2 + 1] = l1;
    }
    // ---- stage W tile (64 x 128 f32) split into bf16x2 hi/lo ----
    for (int idx = tid; idx < 64 * 32; idx += 256) {
        int r = idx >> 5, q = idx & 31;
        int gc = col0 + r;
        const float* src = (gc < DOUT) ? (Wl + gc * K) : (Wr + (gc - DOUT) * K);
        float4 v = *(const float4*)(src + q * 4);
        uint32_t h0, l0, h1, l1;
        split_bf16x2(v.x, v.y, h0, l0);
        split_bf16x2(v.z, v.w, h1, l1);
        sm[WHI + r * PP + q * 2]     = h0;
        sm[WHI + r * PP + q * 2 + 1] = h1;
        sm[WLO + r * PP + q * 2]     = l0;
        sm[WLO + r * PP + q * 2 + 1] = l1;
    }
    __syncthreads();

    const int r8 = lane >> 2;    // 0..7
    const int c4 = lane & 3;     // 0..3

    float acc[2][4][4];
#pragma unroll
    for (int mt = 0; mt < 2; mt++)
#pragma unroll
        for (int nt = 0; nt < 4; nt++)
#pragma unroll
            for (int j = 0; j < 4; j++) acc[mt][nt][j] = 0.f;

#pragma unroll
    for (int kt = 0; kt < 8; kt++) {
        const int kp0 = kt * 8;             // kpair base (16 k values)
        uint32_t ahi[2][4], alo[2][4];
#pragma unroll
        for (int mt = 0; mt < 2; mt++) {
            int rb = mwarp * 32 + mt * 16;
            int o0 = (rb + r8)     * PP + kp0 + c4;
            int o1 = (rb + r8 + 8) * PP + kp0 + c4;
            ahi[mt][0] = sm[XHI + o0];
            ahi[mt][1] = sm[XHI + o1];
            ahi[mt][2] = sm[XHI + o0 + 4];
            ahi[mt][3] = sm[XHI + o1 + 4];
            alo[mt][0] = sm[XLO + o0];
            alo[mt][1] = sm[XLO + o1];
            alo[mt][2] = sm[XLO + o0 + 4];
            alo[mt][3] = sm[XLO + o1 + 4];
        }
        uint32_t bhi[4][2], blo[4][2];
#pragma unroll
        for (int nt = 0; nt < 4; nt++) {
            int nb = (nwarp * 32 + nt * 8 + r8) * PP + kp0 + c4;
            bhi[nt][0] = sm[WHI + nb];
            bhi[nt][1] = sm[WHI + nb + 4];
            blo[nt][0] = sm[WLO + nb];
            blo[nt][1] = sm[WLO + nb + 4];
        }
#pragma unroll
        for (int mt = 0; mt < 2; mt++)
#pragma unroll
            for (int nt = 0; nt < 4; nt++) {
                mma_bf16(acc[mt][nt], ahi[mt], bhi[nt]);
                mma_bf16(acc[mt][nt], alo[mt], bhi[nt]);
                mma_bf16(acc[mt][nt], ahi[mt], blo[nt]);
            }
    }

    // ---- epilogue: scatter accumulators to g_yl / g_yr ----
#pragma unroll
    for (int mt = 0; mt < 2; mt++) {
        int rowg0 = row0 + mwarp * 32 + mt * 16 + r8;
#pragma unroll
        for (int nt = 0; nt < 4; nt++) {
            int colq = col0 + nwarp * 32 + nt * 8 + 2 * c4;   // within D2
            float* dstbase;
            int col;
            if (colq < DOUT) { dstbase = g_yl; col = colq; }
            else             { dstbase = g_yr; col = colq - DOUT; }
            if (rowg0 < NN)
                *(float2*)(dstbase + rowg0 * DOUT + col)
                    = make_float2(acc[mt][nt][0], acc[mt][nt][1]);
            if (rowg0 + 8 < NN)
                *(float2*)(dstbase + (rowg0 + 8) * DOUT + col)
                    = make_float2(acc[mt][nt][2], acc[mt][nt][3]);
        }
    }
}

// ---------------- fused CSR gather + mean + bias + root + BN (+ReLU) -> g_h ----------------
template <bool RELU>
__global__ void gather_fin128_kernel(const float* __restrict__ bl,
                                     const float* __restrict__ g,
                                     const float* __restrict__ b,
                                     const float* __restrict__ rm,
                                     const float* __restrict__ rv)
{
    int w    = (blockIdx.x * blockDim.x + threadIdx.x) >> 5;
    int lane = threadIdx.x & 31;
    if (w >= NN) return;

    int beg = g_rowptr[w];
    int end = g_rowptr[w + 1];

    const float4* yl4 = (const float4*)g_yl;
    float4 acc = make_float4(0.f, 0.f, 0.f, 0.f);

    for (int base = beg; base < end; base += 32) {
        int n  = min(32, end - base);
        int id = (base + lane < end) ? g_adj[base + lane] : 0;
#pragma unroll 4
        for (int j = 0; j < n; j++) {
            int s = __shfl_sync(0xffffffffu, id, j);
            float4 v = yl4[s * 32 + lane];
            acc.x += v.x; acc.y += v.y; acc.z += v.z; acc.w += v.w;
        }
    }

    float inv = (end > beg) ? 1.0f / (float)(end - beg) : 1.0f;

    float4 BL = ((const float4*)bl)[lane];
    float4 G  = ((const float4*)g )[lane];
    float4 B  = ((const float4*)b )[lane];
    float4 RM = ((const float4*)rm)[lane];
    float4 RV = ((const float4*)rv)[lane];
    float4 y  = ((const float4*)g_yr)[w * 32 + lane];

    float sx = G.x * rsqrtf(RV.x + 1e-5f);
    float sy = G.y * rsqrtf(RV.y + 1e-5f);
    float sz = G.z * rsqrtf(RV.z + 1e-5f);
    float sw = G.w * rsqrtf(RV.w + 1e-5f);

    float4 o;
    o.x = (acc.x * inv + BL.x + y.x - RM.x) * sx + B.x;
    o.y = (acc.y * inv + BL.y + y.y - RM.y) * sy + B.y;
    o.z = (acc.z * inv + BL.z + y.z - RM.z) * sz + B.z;
    o.w = (acc.w * inv + BL.w + y.w - RM.w) * sw + B.w;
    if (RELU) {
        o.x = fmaxf(o.x, 0.f); o.y = fmaxf(o.y, 0.f);
        o.z = fmaxf(o.z, 0.f); o.w = fmaxf(o.w, 0.f);
    }
    ((float4*)g_h)[w * 32 + lane] = o;
}

// ---------------- layer 2: fused gather + finalize + row L2 normalize -> out ----------------
__global__ void gather_fin64_norm_kernel(const float* __restrict__ bl,
                                         const float* __restrict__ g,
                                         const float* __restrict__ b,
                                         const float* __restrict__ rm,
                                         const float* __restrict__ rv,
                                         float* __restrict__ out)
{
    int w    = (blockIdx.x * blockDim.x + threadIdx.x) >> 5;
    int lane = threadIdx.x & 31;
    if (w >= NN) return;

    int beg = g_rowptr[w];
    int end = g_rowptr[w + 1];

    const float2* yl2 = (const float2*)g_yl;
    float2 acc = make_float2(0.f, 0.f);

    for (int base = beg; base < end; base += 32) {
        int n  = min(32, end - base);
        int id = (base + lane < end) ? g_adj[base + lane] : 0;
#pragma unroll 4
        for (int j = 0; j < n; j++) {
            int s = __shfl_sync(0xffffffffu, id, j);
            float2 v = yl2[s * 32 + lane];
            acc.x += v.x; acc.y += v.y;
        }
    }

    float inv = (end > beg) ? 1.0f / (float)(end - beg) : 1.0f;

    float2 BL = ((const float2*)bl)[lane];
    float2 G  = ((const float2*)g )[lane];
    float2 B  = ((const float2*)b )[lane];
    float2 RM = ((const float2*)rm)[lane];
    float2 RV = ((const float2*)rv)[lane];
    float2 y  = ((const float2*)g_yr)[w * 32 + lane];

    float v0 = (acc.x * inv + BL.x + y.x - RM.x) * (G.x * rsqrtf(RV.x + 1e-5f)) + B.x;
    float v1 = (acc.y * inv + BL.y + y.y - RM.y) * (G.y * rsqrtf(RV.y + 1e-5f)) + B.y;

    float s = v0 * v0 + v1 * v1;
#pragma unroll
    for (int off = 16; off > 0; off >>= 1)
        s += __shfl_xor_sync(0xffffffffu, s, off);

    float scale = 1.0f / fmaxf(sqrtf(s), 1e-12f);
    ((float2*)out)[w * 32 + lane] = make_float2(v0 * scale, v1 * scale);
}

// ---------------- launch ----------------
extern "C" void kernel_launch(void* const* d_in, const int* in_sizes, int n_in,
                              void* d_out, int out_size)
{
    const float* x  = (const float*)d_in[0];
    const int*   ei = (const int*)d_in[1];
    auto P = [&](int layer, int j) { return (const float*)d_in[2 + layer * 7 + j]; };
    // j: 0=Wl, 1=bl, 2=Wr, 3=g, 4=b, 5=rm, 6=rv

    const int SMEM = (2 * 128 * 68 + 2 * 64 * 68) * 4;  // 104448 bytes -> 2 CTAs/SM
    cudaFuncSetAttribute(tc_gemm_kernel<128, false>, cudaFuncAttributeMaxDynamicSharedMemorySize, SMEM);
    cudaFuncSetAttribute(tc_gemm_kernel<128, true>,  cudaFuncAttributeMaxDynamicSharedMemorySize, SMEM);
    cudaFuncSetAttribute(tc_gemm_kernel<64,  true>,  cudaFuncAttributeMaxDynamicSharedMemorySize, SMEM);

    const int NT = (NN + 127) / 128;   // 391 M-tiles

    // ---- CSR build (once per call, reused by all layers) ----
    zero_cnt_kernel<<<(NN + 255) / 256, 256>>>();
    hist_kernel<<<(EE + 255) / 256, 256>>>(ei);
    scan_kernel<<<1, 1024>>>();
    fill_kernel<<<(EE + 255) / 256, 256>>>(ei);

    // ---- layer 0 (128 -> 128, relu) ----
    tc_gemm_kernel<128, false><<<dim3(NT, 4), 256, SMEM>>>(x, P(0, 0), P(0, 2));
    gather_fin128_kernel<true><<<(NN + 7) / 8, 256>>>(P(0, 1), P(0, 3), P(0, 4), P(0, 5), P(0, 6));

    // ---- layer 1 (128 -> 128, relu) ----
    tc_gemm_kernel<128, true><<<dim3(NT, 4), 256, SMEM>>>(nullptr, P(1, 0), P(1, 2));
    gather_fin128_kernel<true><<<(NN + 7) / 8, 256>>>(P(1, 1), P(1, 3), P(1, 4), P(1, 5), P(1, 6));

    // ---- layer 2 (128 -> 64, no relu, + L2 normalize) ----
    tc_gemm_kernel<64, true><<<dim3(NT, 2), 256, SMEM>>>(nullptr, P(2, 0), P(2, 2));
    gather_fin64_norm_kernel<<<(NN + 7) / 8, 256>>>(P(2, 1), P(2, 3), P(2, 4), P(2, 5), P(2, 6),
                                                    (float*)d_out);
}

// round 7
// speedup vs baseline: 2.3041x; 1.0037x over previous
#include <cuda_runtime.h>
#include <cuda_bf16.h>
#include <cstdint>

#define NN 50000
#define EE 800000

// ---------------- scratch (static device globals; no allocation) ----------------
__device__ int      g_cnt   [NN];          // zero-initialized at load; re-zeroed by scan
__device__ int      g_rowptr[NN + 1];
__device__ int      g_cursor[NN];
__device__ int      g_adj   [EE];
__device__ uint32_t g_xhi   [NN * 64];     // features as packed bf16x2 hi
__device__ uint32_t g_xlo   [NN * 64];     // features as packed bf16x2 lo
__device__ uint32_t g_whi   [640 * 64];    // all layer weights split (rows: L0 256, L1 256, L2 128)
__device__ uint32_t g_wlo   [640 * 64];
__device__ float    g_yl    [NN * 128];    // neighbor-linear pre-aggregation (f32)
__device__ float    g_yr    [NN * 128];    // root-linear (f32)

// ---------------- bf16 double-split helpers ----------------
__device__ __forceinline__ void split_bf16x2(float v0, float v1,
                                             uint32_t& hi, uint32_t& lo) {
    __nv_bfloat162 h = __floats2bfloat162_rn(v0, v1);
    float2 hf = __bfloat1622float2(h);
    __nv_bfloat162 l = __floats2bfloat162_rn(v0 - hf.x, v1 - hf.y);
    hi = *reinterpret_cast<uint32_t*>(&h);
    lo = *reinterpret_cast<uint32_t*>(&l);
}

__device__ __forceinline__ void mma_bf16(float* d, const uint32_t* a, const uint32_t* b) {
    asm volatile(
        "mma.sync.aligned.m16n8k16.row.col.f32.bf16.bf16.f32 "
        "{%0,%1,%2,%3}, {%4,%5,%6,%7}, {%8,%9}, {%0,%1,%2,%3};"
        : "+f"(d[0]), "+f"(d[1]), "+f"(d[2]), "+f"(d[3])
        : "r"(a[0]), "r"(a[1]), "r"(a[2]), "r"(a[3]), "r"(b[0]), "r"(b[1]));
}

// ---------------- one-shot split of x and all weights into bf16 hi/lo ----------------
__global__ void splitx_kernel(const float* __restrict__ x,
                              const float* __restrict__ Wl0, const float* __restrict__ Wr0,
                              const float* __restrict__ Wl1, const float* __restrict__ Wr1,
                              const float* __restrict__ Wl2, const float* __restrict__ Wr2)
{
    const int i = blockIdx.x * blockDim.x + threadIdx.x;
    const int XW = NN * 32;                    // float4 count for x
    float4 v;
    uint32_t* hi_dst;
    uint32_t* lo_dst;
    if (i < XW) {
        int r = i >> 5, q = i & 31;
        v = *(const float4*)(x + r * 128 + q * 4);
        hi_dst = g_xhi + r * 64 + q * 2;
        lo_dst = g_xlo + r * 64 + q * 2;
    } else {
        int j = i - XW;
        if (j >= 640 * 32) return;
        int wrow = j >> 5, q = j & 31;
        const float* src;
        if (wrow < 256)      src = (wrow < 128) ? (Wl0 + wrow * 128)         : (Wr0 + (wrow - 128) * 128);
        else if (wrow < 512) { int r = wrow - 256; src = (r < 128) ? (Wl1 + r * 128) : (Wr1 + (r - 128) * 128); }
        else                 { int r = wrow - 512; src = (r < 64)  ? (Wl2 + r * 128) : (Wr2 + (r - 64)  * 128); }
        v = *(const float4*)(src + q * 4);
        hi_dst = g_whi + wrow * 64 + q * 2;
        lo_dst = g_wlo + wrow * 64 + q * 2;
    }
    uint32_t h0, l0, h1, l1;
    split_bf16x2(v.x, v.y, h0, l0);
    split_bf16x2(v.z, v.w, h1, l1);
    hi_dst[0] = h0; hi_dst[1] = h1;
    lo_dst[0] = l0; lo_dst[1] = l1;
}

// ---------------- CSR build ----------------
__global__ void hist_kernel(const int* __restrict__ ei) {
    int i = blockIdx.x * blockDim.x + threadIdx.x;
    if (i < EE) atomicAdd(&g_cnt[ei[EE + i]], 1);
}

// scan + re-zero cnt (so hist finds zeros on the next call)
__global__ void __launch_bounds__(1024, 1) scan_kernel() {
    __shared__ int sums[1024];
    const int t  = threadIdx.x;
    const int CH = (NN + 1023) / 1024;   // 49
    const int base = t * CH;
    int s = 0;
    for (int i = 0; i < CH; i++) {
        int idx = base + i;
        if (idx < NN) s += g_cnt[idx];
    }
    sums[t] = s;
    __syncthreads();
    for (int off = 1; off < 1024; off <<= 1) {
        int v = (t >= off) ? sums[t - off] : 0;
        __syncthreads();
        sums[t] += v;
        __syncthreads();
    }
    int run = (t == 0) ? 0 : sums[t - 1];
    for (int i = 0; i < CH; i++) {
        int idx = base + i;
        if (idx < NN) {
            int c = g_cnt[idx];
            g_rowptr[idx] = run;
            g_cursor[idx] = run;
            run += c;
            g_cnt[idx] = 0;
        }
    }
    if (t == 1023) g_rowptr[NN] = run;
}

__global__ void fill_kernel(const int* __restrict__ ei) {
    int i = blockIdx.x * blockDim.x + threadIdx.x;
    if (i < EE) {
        int s = ei[i];
        int d = ei[EE + i];
        int p = atomicAdd(&g_cursor[d], 1);
        g_adj[p] = s;
    }
}

// ---------------- bf16 split mma.sync dual GEMM: [yl|yr] = X @ [Wl|Wr]^T ----------------
// Operands already split in global (g_xhi/lo, g_whi/lo) -> staging is pure uint4 copies.
// Block tile: BM=128 rows x 64 cols. grid = (NT, D2/64).
// 8 warps: 4 (M) x 2 (N), each warp 32x32 via m16n8k16.
// acc += AhiBhi + AloBhi + AhiBlo  (drops lo*lo ~ 2^-18).
template <int DOUT>
__global__ void __launch_bounds__(256, 2)
tc_gemm_kernel(int wrow0)
{
    constexpr int PP  = 68;                 // pitch in u32 (bf16 pairs)
    constexpr int XHI = 0;
    constexpr int XLO = 128 * PP;           // 8704
    constexpr int WHI = 2 * 128 * PP;       // 17408
    constexpr int WLO = 2 * 128 * PP + 64 * PP;   // 21760
    // total u32 = 26112 -> 104448 bytes

    extern __shared__ uint32_t sm[];

    const int tid   = threadIdx.x;
    const int lane  = tid & 31;
    const int wid   = tid >> 5;
    const int mwarp = wid & 3;              // 0..3
    const int nwarp = wid >> 2;             // 0..1
    const int row0  = blockIdx.x * 128;
    const int col0  = blockIdx.y * 64;      // within [0, 2*DOUT)

    // ---- stage X tile (128 rows x 16 uint4 per buffer) ----
    for (int idx = tid; idx < 128 * 16; idx += 256) {
        int r = idx >> 4, q4 = idx & 15;
        int grow = row0 + r;
        uint4 h = make_uint4(0u, 0u, 0u, 0u), l = make_uint4(0u, 0u, 0u, 0u);
        if (grow < NN) {
            h = *(const uint4*)(g_xhi + grow * 64 + q4 * 4);
            l = *(const uint4*)(g_xlo + grow * 64 + q4 * 4);
        }
        *(uint4*)&sm[XHI + r * PP + q4 * 4] = h;
        *(uint4*)&sm[XLO + r * PP + q4 * 4] = l;
    }
    // ---- stage W tile (64 rows x 16 uint4 per buffer) ----
    for (int idx = tid; idx < 64 * 16; idx += 256) {
        int r = idx >> 4, q4 = idx & 15;
        int wrow = wrow0 + col0 + r;
        *(uint4*)&sm[WHI + r * PP + q4 * 4] = *(const uint4*)(g_whi + wrow * 64 + q4 * 4);
        *(uint4*)&sm[WLO + r * PP + q4 * 4] = *(const uint4*)(g_wlo + wrow * 64 + q4 * 4);
    }
    __syncthreads();

    const int r8 = lane >> 2;    // 0..7
    const int c4 = lane & 3;     // 0..3

    float acc[2][4][4];
#pragma unroll
    for (int mt = 0; mt < 2; mt++)
#pragma unroll
        for (int nt = 0; nt < 4; nt++)
#pragma unroll
            for (int j = 0; j < 4; j++) acc[mt][nt][j] = 0.f;

#pragma unroll
    for (int kt = 0; kt < 8; kt++) {
        const int kp0 = kt * 8;             // kpair base (16 k values)
        uint32_t ahi[2][4], alo[2][4];
#pragma unroll
        for (int mt = 0; mt < 2; mt++) {
            int rb = mwarp * 32 + mt * 16;
            int o0 = (rb + r8)     * PP + kp0 + c4;
            int o1 = (rb + r8 + 8) * PP + kp0 + c4;
            ahi[mt][0] = sm[XHI + o0];
            ahi[mt][1] = sm[XHI + o1];
            ahi[mt][2] = sm[XHI + o0 + 4];
            ahi[mt][3] = sm[XHI + o1 + 4];
            alo[mt][0] = sm[XLO + o0];
            alo[mt][1] = sm[XLO + o1];
            alo[mt][2] = sm[XLO + o0 + 4];
            alo[mt][3] = sm[XLO + o1 + 4];
        }
        uint32_t bhi[4][2], blo[4][2];
#pragma unroll
        for (int nt = 0; nt < 4; nt++) {
            int nb = (nwarp * 32 + nt * 8 + r8) * PP + kp0 + c4;
            bhi[nt][0] = sm[WHI + nb];
            bhi[nt][1] = sm[WHI + nb + 4];
            blo[nt][0] = sm[WLO + nb];
            blo[nt][1] = sm[WLO + nb + 4];
        }
#pragma unroll
        for (int mt = 0; mt < 2; mt++)
#pragma unroll
            for (int nt = 0; nt < 4; nt++) {
                mma_bf16(acc[mt][nt], ahi[mt], bhi[nt]);
                mma_bf16(acc[mt][nt], alo[mt], bhi[nt]);
                mma_bf16(acc[mt][nt], ahi[mt], blo[nt]);
            }
    }

    // ---- epilogue: scatter accumulators to g_yl / g_yr ----
#pragma unroll
    for (int mt = 0; mt < 2; mt++) {
        int rowg0 = row0 + mwarp * 32 + mt * 16 + r8;
#pragma unroll
        for (int nt = 0; nt < 4; nt++) {
            int colq = col0 + nwarp * 32 + nt * 8 + 2 * c4;   // within D2
            float* dstbase;
            int col;
            if (colq < DOUT) { dstbase = g_yl; col = colq; }
            else             { dstbase = g_yr; col = colq - DOUT; }
            if (rowg0 < NN)
                *(float2*)(dstbase + rowg0 * DOUT + col)
                    = make_float2(acc[mt][nt][0], acc[mt][nt][1]);
            if (rowg0 + 8 < NN)
                *(float2*)(dstbase + (rowg0 + 8) * DOUT + col)
                    = make_float2(acc[mt][nt][2], acc[mt][nt][3]);
        }
    }
}

// ---------------- fused CSR gather + mean + bias + root + BN + ReLU -> split h ----------------
__global__ void gather_fin128_kernel(const float* __restrict__ bl,
                                     const float* __restrict__ g,
                                     const float* __restrict__ b,
                                     const float* __restrict__ rm,
                                     const float* __restrict__ rv)
{
    int w    = (blockIdx.x * blockDim.x + threadIdx.x) >> 5;
    int lane = threadIdx.x & 31;
    if (w >= NN) return;

    int beg = g_rowptr[w];
    int end = g_rowptr[w + 1];

    const float4* yl4 = (const float4*)g_yl;
    float4 acc = make_float4(0.f, 0.f, 0.f, 0.f);

    for (int base = beg; base < end; base += 32) {
        int n  = min(32, end - base);
        int id = (base + lane < end) ? g_adj[base + lane] : 0;
#pragma unroll 8
        for (int j = 0; j < n; j++) {
            int s = __shfl_sync(0xffffffffu, id, j);
            float4 v = yl4[s * 32 + lane];
            acc.x += v.x; acc.y += v.y; acc.z += v.z; acc.w += v.w;
        }
    }

    float inv = (end > beg) ? 1.0f / (float)(end - beg) : 1.0f;

    float4 BL = ((const float4*)bl)[lane];
    float4 G  = ((const float4*)g )[lane];
    float4 B  = ((const float4*)b )[lane];
    float4 RM = ((const float4*)rm)[lane];
    float4 RV = ((const float4*)rv)[lane];
    float4 y  = ((const float4*)g_yr)[w * 32 + lane];

    float sx = G.x * rsqrtf(RV.x + 1e-5f);
    float sy = G.y * rsqrtf(RV.y + 1e-5f);
    float sz = G.z * rsqrtf(RV.z + 1e-5f);
    float sw = G.w * rsqrtf(RV.w + 1e-5f);

    float4 o;
    o.x = fmaxf((acc.x * inv + BL.x + y.x - RM.x) * sx + B.x, 0.f);
    o.y = fmaxf((acc.y * inv + BL.y + y.y - RM.y) * sy + B.y, 0.f);
    o.z = fmaxf((acc.z * inv + BL.z + y.z - RM.z) * sz + B.z, 0.f);
    o.w = fmaxf((acc.w * inv + BL.w + y.w - RM.w) * sw + B.w, 0.f);

    // write next-layer features pre-split (hi/lo bf16x2)
    uint32_t h0, l0, h1, l1;
    split_bf16x2(o.x, o.y, h0, l0);
    split_bf16x2(o.z, o.w, h1, l1);
    g_xhi[w * 64 + 2 * lane]     = h0;
    g_xhi[w * 64 + 2 * lane + 1] = h1;
    g_xlo[w * 64 + 2 * lane]     = l0;
    g_xlo[w * 64 + 2 * lane + 1] = l1;
}

// ---------------- layer 2: fused gather + finalize + row L2 normalize -> out ----------------
__global__ void gather_fin64_norm_kernel(const float* __restrict__ bl,
                                         const float* __restrict__ g,
                                         const float* __restrict__ b,
                                         const float* __restrict__ rm,
                                         const float* __restrict__ rv,
                                         float* __restrict__ out)
{
    int w    = (blockIdx.x * blockDim.x + threadIdx.x) >> 5;
    int lane = threadIdx.x & 31;
    if (w >= NN) return;

    int beg = g_rowptr[w];
    int end = g_rowptr[w + 1];

    const float2* yl2 = (const float2*)g_yl;
    float2 acc = make_float2(0.f, 0.f);

    for (int base = beg; base < end; base += 32) {
        int n  = min(32, end - base);
        int id = (base + lane < end) ? g_adj[base + lane] : 0;
#pragma unroll 8
        for (int j = 0; j < n; j++) {
            int s = __shfl_sync(0xffffffffu, id, j);
            float2 v = yl2[s * 32 + lane];
            acc.x += v.x; acc.y += v.y;
        }
    }

    float inv = (end > beg) ? 1.0f / (float)(end - beg) : 1.0f;

    float2 BL = ((const float2*)bl)[lane];
    float2 G  = ((const float2*)g )[lane];
    float2 B  = ((const float2*)b )[lane];
    float2 RM = ((const float2*)rm)[lane];
    float2 RV = ((const float2*)rv)[lane];
    float2 y  = ((const float2*)g_yr)[w * 32 + lane];

    float v0 = (acc.x * inv + BL.x + y.x - RM.x) * (G.x * rsqrtf(RV.x + 1e-5f)) + B.x;
    float v1 = (acc.y * inv + BL.y + y.y - RM.y) * (G.y * rsqrtf(RV.y + 1e-5f)) + B.y;

    float s = v0 * v0 + v1 * v1;
#pragma unroll
    for (int off = 16; off > 0; off >>= 1)
        s += __shfl_xor_sync(0xffffffffu, s, off);

    float scale = 1.0f / fmaxf(sqrtf(s), 1e-12f);
    ((float2*)out)[w * 32 + lane] = make_float2(v0 * scale, v1 * scale);
}

// ---------------- launch ----------------
extern "C" void kernel_launch(void* const* d_in, const int* in_sizes, int n_in,
                              void* d_out, int out_size)
{
    const float* x  = (const float*)d_in[0];
    const int*   ei = (const int*)d_in[1];
    auto P = [&](int layer, int j) { return (const float*)d_in[2 + layer * 7 + j]; };
    // j: 0=Wl, 1=bl, 2=Wr, 3=g, 4=b, 5=rm, 6=rv

    const int SMEM = (2 * 128 * 68 + 2 * 64 * 68) * 4;  // 104448 bytes -> 2 CTAs/SM
    cudaFuncSetAttribute(tc_gemm_kernel<128>, cudaFuncAttributeMaxDynamicSharedMemorySize, SMEM);
    cudaFuncSetAttribute(tc_gemm_kernel<64>,  cudaFuncAttributeMaxDynamicSharedMemorySize, SMEM);

    const int NT = (NN + 127) / 128;   // 391 M-tiles
    const int SPLIT_N = NN * 32 + 640 * 32;

    // (1) split x + all weights into bf16 hi/lo
    splitx_kernel<<<(SPLIT_N + 255) / 256, 256>>>(x, P(0,0), P(0,2), P(1,0), P(1,2), P(2,0), P(2,2));
    // (2-3) CSR: hist + scan(re-zero)
    hist_kernel<<<(EE + 255) / 256, 256>>>(ei);
    scan_kernel<<<1, 1024>>>();
    // (4) layer-0 GEMM  <- ncu capture slot
    tc_gemm_kernel<128><<<dim3(NT, 4), 256, SMEM>>>(0);
    // (5) CSR fill
    fill_kernel<<<(EE + 255) / 256, 256>>>(ei);
    // layer 0 gather/finalize -> split h1
    gather_fin128_kernel<<<(NN + 7) / 8, 256>>>(P(0,1), P(0,3), P(0,4), P(0,5), P(0,6));
    // layer 1
    tc_gemm_kernel<128><<<dim3(NT, 4), 256, SMEM>>>(256);
    gather_fin128_kernel<<<(NN + 7) / 8, 256>>>(P(1,1), P(1,3), P(1,4), P(1,5), P(1,6));
    // layer 2
    tc_gemm_kernel<64><<<dim3(NT, 2), 256, SMEM>>>(512);
    gather_fin64_norm_kernel<<<(NN + 7) / 8, 256>>>(P(2,1), P(2,3), P(2,4), P(2,5), P(2,6),
                                                    (float*)d_out);
}